// round 16
// baseline (speedup 1.0000x reference)
#include <cuda_runtime.h>
#include <cstdint>

// 2D acoustic FDTD, 4 shots x 512 steps, 256x256 grid.
// R16: NO clusters. 128 plain CTAs (4 shots x 32 slabs of 8 rows) x 512
// threads; grid < #SMs so all CTAs are co-resident in wave 1. NG=4 row
// groups x RPT=2 rows/thread, packed f32x2 math (proven inner loop).
// ALL slab seams cross L2 via self-validating 8-byte words: each u64 packs
// (tag32 << 32 | float_bits) -- single-copy atomic, so one volatile v2.u64
// load fetches both halo floats AND their tags in one L2 round trip. Tags
// are monotonic epoch counts (g_epoch bumped once per launch): replay-safe,
// no reset, no fences. Boundary-first scheduling gives each seam a full
// step of slack.

#define NS    4
#define NT    512
#define NZ    256
#define NX    256
#define NR    128
#define S     260          // padded row stride: cols [2..257] live, pads 0
#define NG    4            // row groups (512 threads / 128 col-pairs)
#define RPT   2            // rows per thread
#define RPC   8            // rows per CTA
#define ROWS  10           // owned rows 1..8; rows 0/9 stay zero (edges)
#define NB    31           // seams per shot

typedef unsigned long long u64;

// seam words: [shot][boundary][dir 0=down-flow,1=up-flow][parity][column]
__device__ __align__(16) u64 gw[NS][NB][2][2][256];
__device__ unsigned int g_epoch;

// ---- packed f32x2 helpers ----
__device__ __forceinline__ u64 f2pack(float lo, float hi) {
    u64 r; asm("mov.b64 %0, {%1, %2};" : "=l"(r) : "f"(lo), "f"(hi)); return r;
}
__device__ __forceinline__ void f2unpack(u64 v, float& lo, float& hi) {
    asm("mov.b64 {%0, %1}, %2;" : "=f"(lo), "=f"(hi) : "l"(v));
}
__device__ __forceinline__ u64 f2add(u64 a, u64 b) {
    u64 r; asm("add.rn.f32x2 %0, %1, %2;" : "=l"(r) : "l"(a), "l"(b)); return r;
}
__device__ __forceinline__ u64 f2mul(u64 a, u64 b) {
    u64 r; asm("mul.rn.f32x2 %0, %1, %2;" : "=l"(r) : "l"(a), "l"(b)); return r;
}
__device__ __forceinline__ u64 f2fma(u64 a, u64 b, u64 c) {
    u64 r; asm("fma.rn.f32x2 %0, %1, %2, %3;" : "=l"(r) : "l"(a), "l"(b), "l"(c)); return r;
}
__device__ __forceinline__ u64 f2ld(const float* p) {        // aligned LDS.64
    float2 v = *(const float2*)p; return f2pack(v.x, v.y);
}
__device__ __forceinline__ void f2st(float* p, u64 v) {      // aligned STS.64
    float lo, hi; f2unpack(v, lo, hi);
    *(float2*)p = make_float2(lo, hi);
}

// ---- seam word ops: one 16B volatile access carries 2x (tag, value) ----
__device__ __forceinline__ u64 seam_wait(const u64* p, unsigned int want) {
    u64 x, y;
    while (true) {
        asm volatile("ld.volatile.global.v2.u64 {%0, %1}, [%2];"
                     : "=l"(x), "=l"(y) : "l"(p) : "memory");
        if ((int)((unsigned int)(x >> 32) - want) >= 0 &&
            (int)((unsigned int)(y >> 32) - want) >= 0) break;
    }
    // pair = (lo float bits, hi float bits)
    return (x & 0xffffffffull) | (y << 32);
}
__device__ __forceinline__ void seam_pub(u64* p, unsigned int tag, u64 pair) {
    u64 x = ((u64)tag << 32) | (pair & 0xffffffffull);
    u64 y = ((u64)tag << 32) | (pair >> 32);
    asm volatile("st.volatile.global.v2.u64 [%0], {%1, %2};"
                 :: "l"(p), "l"(x), "l"(y) : "memory");
}

__global__ void __launch_bounds__(512, 2)
wave_kernel(const float* __restrict__ xin,   // (NS, NT)
            const float* __restrict__ vp,    // (NZ, NX)
            const int*   __restrict__ src_z, // (NS,)
            const int*   __restrict__ src_x, // (NS,)
            const int*   __restrict__ rec_z, // (NS, NR)
            const int*   __restrict__ rec_x, // (NS, NR)
            float*       __restrict__ out)   // (NS, NT, NR, 1)
{
    __shared__ float smem[2 * ROWS * S];
    __shared__ float sxin[NT];
    __shared__ int   rcnt;
    __shared__ int   rpos[NR];
    __shared__ short rid[NR];
    __shared__ unsigned int s_eb;

    const int tid = threadIdx.x;
    const int g   = tid >> 7;           // row group 0..3
    const int tx  = tid & 127;          // column-pair index
    const int xi  = 2 + 2 * tx;
    const int bid = blockIdx.x;
    const int s   = bid >> 5;           // shot
    const int b   = bid & 31;           // slab 0..31
    const int r0  = b * RPC;
    const int gz0 = g * RPT;

    for (int i = tid; i < 2 * ROWS * S; i += 512) smem[i] = 0.0f;
    sxin[tid] = (xin[s * NT + tid] * 0.001f) * 0.001f;   // 512 == NT
    if (tid == 0) {
        rcnt = 0;
        asm volatile("ld.global.cg.b32 %0, [%1];" : "=r"(s_eb)
                     : "l"(&g_epoch) : "memory");
    }
    __syncthreads();

    if (tid < NR) {
        int rz = rec_z[s * NR + tid];
        if (rz >= r0 && rz < r0 + RPC) {
            int i = atomicAdd(&rcnt, 1);
            rpos[i] = (rz - r0 + 1) * S + rec_x[s * NR + tid] + 2;
            rid[i]  = (short)tid;
        }
    }

    const int  srcz    = src_z[s];
    const int  srcx    = src_x[s];
    const int  szc     = srcz - r0;
    const bool my_src  = (szc >= gz0 && szc < gz0 + RPT) && (tx == (srcx >> 1));
    const int  szl     = szc - gz0;
    const int  srclane = srcx & 1;

    u64 c2p[RPT], ccp[RPT], nco[RPT];
#pragma unroll
    for (int z = 0; z < RPT; z++) {
        float a0 = vp[(r0 + gz0 + z) * NX + 2 * tx]     * 0.001f;
        float a1 = vp[(r0 + gz0 + z) * NX + 2 * tx + 1] * 0.001f;
        c2p[z] = f2pack((a0 * a0) * 0.01f, (a1 * a1) * 0.01f);
        ccp[z] = 0ull;
        nco[z] = 0ull;                  // -p_{t-1}
    }
    __syncthreads();                    // rcnt/rpos/rid + sxin + s_eb final

    const unsigned int ebase = s_eb;
    const bool has_rec = (tid < rcnt);
    const int  myrpos  = has_rec ? rpos[tid] : 0;
    float*     outp    = out + (size_t)s * NT * NR + (has_rec ? (int)rid[tid] : 0);

    const bool has_up = (b > 0);
    const bool has_dn = (b < 31);
    const bool gtop   = (g == 0);
    const bool gbot   = (g == NG - 1);

    // seam word pointers for this thread (2 consecutive u64 = one v2 access)
    // top of CTA (g0): consume dir0 @ boundary b-1, publish dir1 there.
    // bottom of CTA (g3): consume dir1 @ boundary b, publish dir0 there.
    const u64* cw[2] = { nullptr, nullptr };
    u64*       pw[2] = { nullptr, nullptr };
    if (gtop && has_up) {
        cw[0] = &gw[s][b-1][0][0][2*tx]; cw[1] = &gw[s][b-1][0][1][2*tx];
        pw[0] = &gw[s][b-1][1][0][2*tx]; pw[1] = &gw[s][b-1][1][1][2*tx];
    }
    if (gbot && has_dn) {
        cw[0] = &gw[s][b][1][0][2*tx]; cw[1] = &gw[s][b][1][1][2*tx];
        pw[0] = &gw[s][b][0][0][2*tx]; pw[1] = &gw[s][b][0][1][2*tx];
    }

    float* const b0p = smem;
    float* const b1p = smem + ROWS * S;

    const u64 NEG4 = f2pack(-4.0f, -4.0f);
    const u64 TWO  = f2pack( 2.0f,  2.0f);
    const u64 NEG1 = f2pack(-1.0f, -1.0f);

    const int off0  = (gz0 + 1) * S + xi;
    const int offSB = gz0 * S + xi;
    const int offSA = (gz0 + RPT + 1) * S + xi;

#define STEP_ROW(PN, z, below, above, oldcc, val)                              \
    {                                                                          \
        u64 cc = ccp[z];                                                       \
        float clo, chi; f2unpack(cc, clo, chi);                                \
        u64 vert = f2add(below, above);                                        \
        u64 horz = f2pack(lv[z] + chi, clo + rv[z]);                           \
        u64 lap  = f2fma(cc, NEG4, f2add(vert, horz));                         \
        u64 tmp  = f2fma(cc, TWO, nco[z]);                                     \
        val = f2fma(c2p[z], lap, tmp);                                         \
        nco[z] = f2mul(cc, NEG1);                                              \
        if (my_src && (z) == szl) {                                            \
            float a, b2; f2unpack(val, a, b2);                                 \
            if (srclane) b2 += srcval; else a += srcval;                       \
            val = f2pack(a, b2);                                               \
        }                                                                      \
        ccp[z] = val;                                                          \
        f2st((PN) + off0 + (z) * S, val);                                      \
        oldcc = cc;                                                            \
    }

// One step, boundary-first: wait seam -> boundary row -> publish -> rest.
#define DO_STEP(PCUR, PNXT, PAR, T, WAITOK, OUTOFF)                            \
    {                                                                          \
        float srcval = 0.0f;                                                   \
        if (my_src) srcval = sxin[T];                                          \
        float lv[RPT], rv[RPT];                                                \
        _Pragma("unroll")                                                      \
        for (int z = 0; z < RPT; z++) {                                        \
            float2 a = *(const float2*)((PCUR) + off0 + z * S - 2);            \
            float2 bb = *(const float2*)((PCUR) + off0 + z * S + 2);           \
            lv[z] = a.y; rv[z] = bb.x;                                         \
        }                                                                      \
        u64 oldcc, val;                                                        \
        if (gtop) {                                                            \
            const u64 seamA = f2ld((PCUR) + offSA);                            \
            const u64 save0 = ccp[0];                                          \
            const u64 save1 = ccp[1];                                          \
            u64 below0;                                                        \
            if (has_up) {                                                      \
                below0 = (WAITOK)                                              \
                    ? seam_wait(cw[(PAR) ^ 1], ebase + (unsigned int)(T))      \
                    : 0ull;                                                    \
            } else below0 = f2ld((PCUR) + offSB);   /* zero halo row */        \
            STEP_ROW(PNXT, 0, below0, save1, oldcc, val);                      \
            if (has_up) seam_pub(pw[PAR], ebase + (unsigned int)(T) + 1u, val);\
            STEP_ROW(PNXT, 1, save0, seamA, oldcc, val);                       \
        } else if (gbot) {                                                     \
            const u64 seamB = f2ld((PCUR) + offSB);                            \
            const u64 saveL = ccp[RPT - 1];                                    \
            u64 belowB = ccp[RPT - 2];                                         \
            u64 above1;                                                        \
            if (has_dn) {                                                      \
                above1 = (WAITOK)                                              \
                    ? seam_wait(cw[(PAR) ^ 1], ebase + (unsigned int)(T))      \
                    : 0ull;                                                    \
            } else above1 = f2ld((PCUR) + offSA);   /* zero halo row */        \
            STEP_ROW(PNXT, RPT - 1, belowB, above1, oldcc, val);               \
            if (has_dn) seam_pub(pw[PAR], ebase + (unsigned int)(T) + 1u, val);\
            STEP_ROW(PNXT, 0, seamB, saveL, oldcc, val);                       \
        } else {                                                               \
            const u64 seamA = f2ld((PCUR) + offSA);                            \
            u64 below = f2ld((PCUR) + offSB);                                  \
            _Pragma("unroll")                                                  \
            for (int z = 0; z < RPT; z++) {                                    \
                u64 above = (z == RPT - 1) ? seamA : ccp[z + 1];               \
                STEP_ROW(PNXT, z, below, above, oldcc, val);                   \
                below = oldcc;                                                 \
            }                                                                  \
        }                                                                      \
        __syncthreads();                                                       \
        if (has_rec) outp[OUTOFF] = (PNXT)[myrpos];                            \
    }

    for (int t = 0; t < NT; t += 4) {
        DO_STEP(b0p, b1p, 0, t,     t > 0, 0);
        DO_STEP(b1p, b0p, 1, t + 1, true,  NR);
        DO_STEP(b0p, b1p, 0, t + 2, true,  2 * NR);
        DO_STEP(b1p, b0p, 1, t + 3, true,  3 * NR);
        outp += 4 * NR;
    }

    // advance epoch once per launch (stream order protects the next launch;
    // all CTAs read g_epoch at entry, long before any CTA can finish)
    if (bid == 0 && tid == 0) atomicAdd(&g_epoch, (unsigned int)NT);
#undef DO_STEP
#undef STEP_ROW
}

extern "C" void kernel_launch(void* const* d_in, const int* in_sizes, int n_in,
                              void* d_out, int out_size)
{
    const float* x     = (const float*)d_in[0];
    const float* vp    = (const float*)d_in[1];
    const int*   src_z = (const int*)d_in[2];
    const int*   src_x = (const int*)d_in[3];
    const int*   rec_z = (const int*)d_in[4];
    const int*   rec_x = (const int*)d_in[5];
    float*       out   = (float*)d_out;

    wave_kernel<<<NS * 32, 512>>>(x, vp, src_z, src_x, rec_z, rec_x, out);
}

// round 17
// speedup vs baseline: 1.0105x; 1.0105x over previous
#include <cuda_runtime.h>
#include <cstdint>

// 2D acoustic FDTD, 4 shots x 512 steps, 256x256 grid.
// R17: 16 clusters x 8 CTAs x 512 threads (128 CTAs, 2-CTA/SM RF headroom
// via __launch_bounds__(512,2) so the cluster probe passes). 8 rows/CTA,
// NG=4 groups x RPT=2 row-pairs (proven loop). Intra-cluster halos (7 of 8
// boundaries) via st.async.b64 + parity mbarriers (proven, ~free). The 3
// remaining L2 seams per shot use R16's proven self-validating packed
// (tag|value) words: one volatile v2.u64 load = data + tags in one L2 trip;
// monotonic epoch tags -> graph-replay safe. Fallback: proven R11 kernel.

#define NS    4
#define NT    512
#define NZ    256
#define NX    256
#define NR    128
#define S     260          // padded row stride: cols [2..257] live, pads 0

typedef unsigned long long u64;

// L2 seam words: [shot][boundary 0..2][dir 0=down-flow,1=up-flow][par][col]
__device__ __align__(16) u64 gw[NS][3][2][2][256];
__device__ unsigned int g_epoch;

__device__ __forceinline__ uint32_t smem_u32(const void* p) {
    uint32_t a;
    asm("{ .reg .u64 t; cvta.to.shared.u64 t, %1; cvt.u32.u64 %0, t; }"
        : "=r"(a) : "l"(p));
    return a;
}
__device__ __forceinline__ uint32_t mapa32(uint32_t laddr, uint32_t rank) {
    uint32_t ra;
    asm("mapa.shared::cluster.u32 %0, %1, %2;" : "=r"(ra) : "r"(laddr), "r"(rank));
    return ra;
}
__device__ __forceinline__ void mbar_init(uint32_t mbar, uint32_t cnt) {
    asm volatile("mbarrier.init.shared::cta.b64 [%0], %1;" :: "r"(mbar), "r"(cnt) : "memory");
}
__device__ __forceinline__ void mbar_expect(uint32_t mbar, uint32_t tx) {
    asm volatile("mbarrier.arrive.expect_tx.shared::cta.b64 _, [%0], %1;"
                 :: "r"(mbar), "r"(tx) : "memory");
}
__device__ __forceinline__ void mbar_wait(uint32_t mbar, uint32_t parity) {
    asm volatile(
        "{\n\t"
        ".reg .pred P;\n\t"
        "LW%=:\n\t"
        "mbarrier.try_wait.parity.acquire.cluster.shared::cta.b64 P, [%0], %1;\n\t"
        "@P bra LD%=;\n\t"
        "bra LW%=;\n\t"
        "LD%=:\n\t"
        "}"
        :: "r"(mbar), "r"(parity) : "memory");
}
__device__ __forceinline__ void st_async_f2(uint32_t rslot, uint32_t rmbar, u64 v) {
    asm volatile("st.async.shared::cluster.mbarrier::complete_tx::bytes.b64 [%0], %1, [%2];"
                 :: "r"(rslot), "l"(v), "r"(rmbar) : "memory");
}
__device__ __forceinline__ void cluster_sync_() {
    asm volatile("barrier.cluster.arrive.aligned;" ::: "memory");
    asm volatile("barrier.cluster.wait.aligned;" ::: "memory");
}

// ---- packed f32x2 helpers ----
__device__ __forceinline__ u64 f2pack(float lo, float hi) {
    u64 r; asm("mov.b64 %0, {%1, %2};" : "=l"(r) : "f"(lo), "f"(hi)); return r;
}
__device__ __forceinline__ void f2unpack(u64 v, float& lo, float& hi) {
    asm("mov.b64 {%0, %1}, %2;" : "=f"(lo), "=f"(hi) : "l"(v));
}
__device__ __forceinline__ u64 f2add(u64 a, u64 b) {
    u64 r; asm("add.rn.f32x2 %0, %1, %2;" : "=l"(r) : "l"(a), "l"(b)); return r;
}
__device__ __forceinline__ u64 f2mul(u64 a, u64 b) {
    u64 r; asm("mul.rn.f32x2 %0, %1, %2;" : "=l"(r) : "l"(a), "l"(b)); return r;
}
__device__ __forceinline__ u64 f2fma(u64 a, u64 b, u64 c) {
    u64 r; asm("fma.rn.f32x2 %0, %1, %2, %3;" : "=l"(r) : "l"(a), "l"(b), "l"(c)); return r;
}
__device__ __forceinline__ u64 f2ld(const float* p) {
    float2 v = *(const float2*)p; return f2pack(v.x, v.y);
}
__device__ __forceinline__ void f2st(float* p, u64 v) {
    float lo, hi; f2unpack(v, lo, hi);
    *(float2*)p = make_float2(lo, hi);
}

// ---- L2 seam word ops (proven in R16) ----
__device__ __forceinline__ u64 seam_wait(const u64* p, unsigned int want) {
    u64 x, y;
    while (true) {
        asm volatile("ld.volatile.global.v2.u64 {%0, %1}, [%2];"
                     : "=l"(x), "=l"(y) : "l"(p) : "memory");
        if ((int)((unsigned int)(x >> 32) - want) >= 0 &&
            (int)((unsigned int)(y >> 32) - want) >= 0) break;
    }
    return (x & 0xffffffffull) | (y << 32);
}
__device__ __forceinline__ void seam_pub(u64* p, unsigned int tag, u64 pair) {
    u64 x = ((u64)tag << 32) | (pair & 0xffffffffull);
    u64 y = ((u64)tag << 32) | (pair >> 32);
    asm volatile("st.volatile.global.v2.u64 [%0], {%1, %2};"
                 :: "l"(p), "l"(x), "l"(y) : "memory");
}

// ============================ R17 CLUSTER KERNEL ==========================
#define NGc   4
#define RPTc  2
#define RPCc  8
#define ROWSc 10

__global__ void __launch_bounds__(512, 2) __cluster_dims__(8, 1, 1)
wave_cl8(const float* __restrict__ xin,
         const float* __restrict__ vp,
         const int*   __restrict__ src_z,
         const int*   __restrict__ src_x,
         const int*   __restrict__ rec_z,
         const int*   __restrict__ rec_x,
         float*       __restrict__ out)
{
    __shared__ float smem[2 * ROWSc * S];
    __shared__ __align__(8) uint64_t mbars[4];
    __shared__ float sxin[NT];
    __shared__ int   rcnt;
    __shared__ int   rpos[NR];
    __shared__ short rid[NR];
    __shared__ unsigned int s_eb;

    const int tid = threadIdx.x;
    const int g   = tid >> 7;           // row group 0..3
    const int tx  = tid & 127;
    const int xi  = 2 + 2 * tx;
    const int bid = blockIdx.x;
    const int s   = bid >> 5;           // shot
    const int b   = bid & 31;           // slab 0..31
    uint32_t rank;
    asm("mov.u32 %0, %%cluster_ctarank;" : "=r"(rank));   // == b & 7
    const int r0  = b * RPCc;
    const int gz0 = g * RPTc;

    for (int i = tid; i < 2 * ROWSc * S; i += 512) smem[i] = 0.0f;
    sxin[tid] = (xin[s * NT + tid] * 0.001f) * 0.001f;    // 512 == NT
    if (tid == 0) {
        rcnt = 0;
        for (int i = 0; i < 4; i++) mbar_init(smem_u32(&mbars[i]), 1);
        asm volatile("ld.global.cg.b32 %0, [%1];" : "=r"(s_eb)
                     : "l"(&g_epoch) : "memory");
    }
    __syncthreads();
    cluster_sync_();                    // mbars visible cluster-wide

    if (tid < NR) {
        int rz = rec_z[s * NR + tid];
        if (rz >= r0 && rz < r0 + RPCc) {
            int i = atomicAdd(&rcnt, 1);
            rpos[i] = (rz - r0 + 1) * S + rec_x[s * NR + tid] + 2;
            rid[i]  = (short)tid;
        }
    }

    const int  srcz    = src_z[s];
    const int  srcx    = src_x[s];
    const int  szc     = srcz - r0;
    const bool my_src  = (szc >= gz0 && szc < gz0 + RPTc) && (tx == (srcx >> 1));
    const int  szl     = szc - gz0;
    const int  srclane = srcx & 1;

    u64 c2p[RPTc], ccp[RPTc], nco[RPTc];
#pragma unroll
    for (int z = 0; z < RPTc; z++) {
        float a0 = vp[(r0 + gz0 + z) * NX + 2 * tx]     * 0.001f;
        float a1 = vp[(r0 + gz0 + z) * NX + 2 * tx + 1] * 0.001f;
        c2p[z] = f2pack((a0 * a0) * 0.01f, (a1 * a1) * 0.01f);
        ccp[z] = 0ull;
        nco[z] = 0ull;
    }
    __syncthreads();

    const unsigned int ebase = s_eb;
    const bool has_rec = (tid < rcnt);
    const int  myrpos  = has_rec ? rpos[tid] : 0;
    float*     outp    = out + (size_t)s * NT * NR + (has_rec ? (int)rid[tid] : 0);

    const bool intra_up = (rank > 0);
    const bool intra_dn = (rank < 7);
    const bool seam_up  = (rank == 0) && (b > 0);
    const bool seam_dn  = (rank == 7) && (b < 31);
    const bool gtop     = (g == 0);
    const bool gbot     = (g == NGc - 1);
    const bool lead_t   = (tid == 0);
    const bool lead_b   = (tid == (NGc - 1) * 128);

    // L2 seam word pointers (only boundary groups of seam CTAs use them)
    const u64* cw[2] = { nullptr, nullptr };
    u64*       pw[2] = { nullptr, nullptr };
    if (gtop && seam_up) {              // boundary (b/8)-1: consume dir0, pub dir1
        const int bd = (b >> 3) - 1;
        cw[0] = &gw[s][bd][0][0][2*tx]; cw[1] = &gw[s][bd][0][1][2*tx];
        pw[0] = &gw[s][bd][1][0][2*tx]; pw[1] = &gw[s][bd][1][1][2*tx];
    }
    if (gbot && seam_dn) {              // boundary b/8: consume dir1, pub dir0
        const int bd = b >> 3;
        cw[0] = &gw[s][bd][1][0][2*tx]; cw[1] = &gw[s][bd][1][1][2*tx];
        pw[0] = &gw[s][bd][0][0][2*tx]; pw[1] = &gw[s][bd][0][1][2*tx];
    }

    float* const b0p = smem;
    float* const b1p = smem + ROWSc * S;
    const uint32_t base0 = smem_u32(b0p);
    const uint32_t base1 = smem_u32(b1p);
    const uint32_t mb_top[2] = { smem_u32(&mbars[0]), smem_u32(&mbars[1]) };
    const uint32_t mb_bot[2] = { smem_u32(&mbars[2]), smem_u32(&mbars[3]) };

    const u64 NEG4 = f2pack(-4.0f, -4.0f);
    const u64 TWO  = f2pack( 2.0f,  2.0f);
    const u64 NEG1 = f2pack(-1.0f, -1.0f);

    const int off0  = (gz0 + 1) * S + xi;
    const int offSB = gz0 * S + xi;
    const int offSA = (gz0 + RPTc + 1) * S + xi;

#define STEP_ROW(PN, z, below, above, oldcc, val)                              \
    {                                                                          \
        u64 cc = ccp[z];                                                       \
        float clo, chi; f2unpack(cc, clo, chi);                                \
        u64 vert = f2add(below, above);                                        \
        u64 horz = f2pack(lv[z] + chi, clo + rv[z]);                           \
        u64 lap  = f2fma(cc, NEG4, f2add(vert, horz));                         \
        u64 tmp  = f2fma(cc, TWO, nco[z]);                                     \
        val = f2fma(c2p[z], lap, tmp);                                         \
        nco[z] = f2mul(cc, NEG1);                                              \
        if (my_src && (z) == szl) {                                            \
            float a, b2; f2unpack(val, a, b2);                                 \
            if (srclane) b2 += srcval; else a += srcval;                       \
            val = f2pack(a, b2);                                               \
        }                                                                      \
        ccp[z] = val;                                                          \
        f2st((PN) + off0 + (z) * S, val);                                      \
        oldcc = cc;                                                            \
    }

#define DO_STEP(PCUR, PNXT, RBASE, PAR, T, WAITOK, WPAR, OUTOFF)               \
    {                                                                          \
        float srcval = 0.0f;                                                   \
        if (my_src) srcval = sxin[T];                                          \
        float lv[RPTc], rv[RPTc];                                              \
        _Pragma("unroll")                                                      \
        for (int z = 0; z < RPTc; z++) {                                       \
            float2 a  = *(const float2*)((PCUR) + off0 + z * S - 2);           \
            float2 bb = *(const float2*)((PCUR) + off0 + z * S + 2);           \
            lv[z] = a.y; rv[z] = bb.x;                                         \
        }                                                                      \
        u64 oldcc, val;                                                        \
        if (gtop) {                                                            \
            if (lead_t && intra_up) mbar_expect(mb_top[PAR], NX * 4);          \
            const u64 seamA = f2ld((PCUR) + offSA);                            \
            const u64 save0 = ccp[0];                                          \
            const u64 save1 = ccp[1];                                          \
            u64 below0;                                                        \
            if (intra_up) {                                                    \
                if (WAITOK) mbar_wait(mb_top[(PAR) ^ 1], (WPAR));              \
                below0 = f2ld((PCUR) + offSB);                                 \
            } else if (seam_up) {                                              \
                below0 = (WAITOK)                                              \
                    ? seam_wait(cw[(PAR) ^ 1], ebase + (unsigned int)(T))      \
                    : 0ull;                                                    \
            } else {                                                           \
                below0 = f2ld((PCUR) + offSB);   /* permanent zero halo */     \
            }                                                                  \
            STEP_ROW(PNXT, 0, below0, save1, oldcc, val);                      \
            if (intra_up) {                                                    \
                uint32_t rs = mapa32((RBASE) +                                 \
                    (uint32_t)((ROWSc - 1) * S + xi) * 4u, rank - 1);          \
                uint32_t rm = mapa32(mb_bot[PAR], rank - 1);                   \
                st_async_f2(rs, rm, val);                                      \
            } else if (seam_up) {                                              \
                seam_pub(pw[PAR], ebase + (unsigned int)(T) + 1u, val);        \
            }                                                                  \
            STEP_ROW(PNXT, 1, save0, seamA, oldcc, val);                       \
        } else if (gbot) {                                                     \
            if (lead_b && intra_dn) mbar_expect(mb_bot[PAR], NX * 4);          \
            const u64 seamB = f2ld((PCUR) + offSB);                            \
            const u64 saveL = ccp[RPTc - 1];                                   \
            u64 belowB = ccp[RPTc - 2];                                        \
            u64 above1;                                                        \
            if (intra_dn) {                                                    \
                if (WAITOK) mbar_wait(mb_bot[(PAR) ^ 1], (WPAR));              \
                above1 = f2ld((PCUR) + offSA);                                 \
            } else if (seam_dn) {                                              \
                above1 = (WAITOK)                                              \
                    ? seam_wait(cw[(PAR) ^ 1], ebase + (unsigned int)(T))      \
                    : 0ull;                                                    \
            } else {                                                           \
                above1 = f2ld((PCUR) + offSA);   /* permanent zero halo */     \
            }                                                                  \
            STEP_ROW(PNXT, RPTc - 1, belowB, above1, oldcc, val);              \
            if (intra_dn) {                                                    \
                uint32_t rs = mapa32((RBASE) + (uint32_t)(xi) * 4u, rank + 1); \
                uint32_t rm = mapa32(mb_top[PAR], rank + 1);                   \
                st_async_f2(rs, rm, val);                                      \
            } else if (seam_dn) {                                              \
                seam_pub(pw[PAR], ebase + (unsigned int)(T) + 1u, val);        \
            }                                                                  \
            STEP_ROW(PNXT, 0, seamB, saveL, oldcc, val);                       \
        } else {                                                               \
            const u64 seamA = f2ld((PCUR) + offSA);                            \
            u64 below = f2ld((PCUR) + offSB);                                  \
            _Pragma("unroll")                                                  \
            for (int z = 0; z < RPTc; z++) {                                   \
                u64 above = (z == RPTc - 1) ? seamA : ccp[z + 1];              \
                STEP_ROW(PNXT, z, below, above, oldcc, val);                   \
                below = oldcc;                                                 \
            }                                                                  \
        }                                                                      \
        __syncthreads();                                                       \
        if (has_rec) outp[OUTOFF] = (PNXT)[myrpos];                            \
    }

    // x4 unroll: phases t mod 4 -> (PAR, WPAR) = (0,1),(1,0),(0,0),(1,1)
    for (int t = 0; t < NT; t += 4) {
        DO_STEP(b0p, b1p, base1, 0, t,     t > 0, 1, 0);
        DO_STEP(b1p, b0p, base0, 1, t + 1, true,  0, NR);
        DO_STEP(b0p, b1p, base1, 0, t + 2, true,  0, 2 * NR);
        DO_STEP(b1p, b0p, base0, 1, t + 3, true,  1, 3 * NR);
        outp += 4 * NR;
    }

    // drain final intra phase (NT-1 = 511: mbar[1], parity 1)
    if (lead_t && intra_up) mbar_wait(mb_top[1], 1);
    if (lead_b && intra_dn) mbar_wait(mb_bot[1], 1);
    __syncthreads();
    cluster_sync_();

    if (bid == 0 && tid == 0) atomicAdd(&g_epoch, (unsigned int)NT);
#undef DO_STEP
#undef STEP_ROW
}

// ========================= FALLBACK KERNEL (R11) ==========================
#define NG    8

template<int CSZ>
__global__ void __launch_bounds__(1024, 1) __cluster_dims__(CSZ, 1, 1)
wave_kernel_fb(const float* __restrict__ xin,
               const float* __restrict__ vp,
               const int*   __restrict__ src_z,
               const int*   __restrict__ src_x,
               const int*   __restrict__ rec_z,
               const int*   __restrict__ rec_x,
               float*       __restrict__ out)
{
    constexpr int RPC  = NZ / CSZ;
    constexpr int RPT  = RPC / NG;
    constexpr int ROWS = RPC + 2;
    extern __shared__ float smem[];
    __shared__ __align__(8) uint64_t mbars[4];
    __shared__ float sxin[NT];
    __shared__ int   rcnt;
    __shared__ int   rpos[NR];
    __shared__ short rid[NR];

    const int tid = threadIdx.x;
    const int g   = tid >> 7;
    const int tx  = tid & 127;
    const int xi  = 2 + 2 * tx;
    const int s   = blockIdx.x / CSZ;
    uint32_t rank;
    asm("mov.u32 %0, %%cluster_ctarank;" : "=r"(rank));
    const int r0  = (int)rank * RPC;
    const int gz0 = g * RPT;

    for (int i = tid; i < 2 * ROWS * S; i += 1024) smem[i] = 0.0f;
    if (tid < NT) sxin[tid] = (xin[s * NT + tid] * 0.001f) * 0.001f;
    if (tid == 0) {
        rcnt = 0;
        for (int i = 0; i < 4; i++) mbar_init(smem_u32(&mbars[i]), 1);
    }
    __syncthreads();
    cluster_sync_();

    if (tid < NR) {
        int rz = rec_z[s * NR + tid];
        if (rz >= r0 && rz < r0 + RPC) {
            int i = atomicAdd(&rcnt, 1);
            rpos[i] = (rz - r0 + 1) * S + rec_x[s * NR + tid] + 2;
            rid[i]  = (short)tid;
        }
    }

    const int  srcz    = src_z[s];
    const int  srcx    = src_x[s];
    const int  szc     = srcz - r0;
    const bool my_src  = (szc >= gz0 && szc < gz0 + RPT) && (tx == (srcx >> 1));
    const int  szl     = szc - gz0;
    const int  srclane = srcx & 1;

    u64 c2p[RPT], ccp[RPT], nco[RPT];
#pragma unroll
    for (int z = 0; z < RPT; z++) {
        float a0 = vp[(r0 + gz0 + z) * NX + 2 * tx]     * 0.001f;
        float a1 = vp[(r0 + gz0 + z) * NX + 2 * tx + 1] * 0.001f;
        c2p[z] = f2pack((a0 * a0) * 0.01f, (a1 * a1) * 0.01f);
        ccp[z] = 0ull;
        nco[z] = 0ull;
    }
    __syncthreads();

    const bool has_rec = (tid < rcnt);
    const int  myrpos  = has_rec ? rpos[tid] : 0;
    float*     outp    = out + (size_t)s * NT * NR + (has_rec ? (int)rid[tid] : 0);

    float* const b0 = smem;
    float* const b1 = smem + ROWS * S;
    const uint32_t base0 = smem_u32(b0);
    const uint32_t base1 = smem_u32(b1);
    const uint32_t mb_top[2] = { smem_u32(&mbars[0]), smem_u32(&mbars[1]) };
    const uint32_t mb_bot[2] = { smem_u32(&mbars[2]), smem_u32(&mbars[3]) };
    const bool has_up = (rank > 0);
    const bool has_dn = (rank < CSZ - 1);
    const bool gtop   = (g == 0);
    const bool gbot   = (g == NG - 1);
    const bool lead_t = (tid == 0);
    const bool lead_b = (tid == (NG - 1) * 128);

    const u64 NEG4 = f2pack(-4.0f, -4.0f);
    const u64 TWO  = f2pack( 2.0f,  2.0f);
    const u64 NEG1 = f2pack(-1.0f, -1.0f);

    const int off0  = (gz0 + 1) * S + xi;
    const int offSB = gz0 * S + xi;
    const int offSA = (gz0 + RPT + 1) * S + xi;

#define STEP_ROW(PN, z, below, above, oldcc, val)                              \
    {                                                                          \
        u64 cc = ccp[z];                                                       \
        float clo, chi; f2unpack(cc, clo, chi);                                \
        u64 vert = f2add(below, above);                                        \
        u64 horz = f2pack(lv[z] + chi, clo + rv[z]);                           \
        u64 lap  = f2fma(cc, NEG4, f2add(vert, horz));                         \
        u64 tmp  = f2fma(cc, TWO, nco[z]);                                     \
        val = f2fma(c2p[z], lap, tmp);                                         \
        nco[z] = f2mul(cc, NEG1);                                              \
        if (my_src && (z) == szl) {                                            \
            float a, b; f2unpack(val, a, b);                                   \
            if (srclane) b += srcval; else a += srcval;                        \
            val = f2pack(a, b);                                                \
        }                                                                      \
        ccp[z] = val;                                                          \
        f2st((PN) + off0 + (z) * S, val);                                      \
        oldcc = cc;                                                            \
    }

#define DO_STEP(PCUR, PNXT, RBASE, PAR, T, WAITOK, WPAR, OUTOFF)               \
    {                                                                          \
        float srcval = 0.0f;                                                   \
        if (my_src) srcval = sxin[T];                                          \
        float lv[RPT], rv[RPT];                                                \
        _Pragma("unroll")                                                      \
        for (int z = 0; z < RPT; z++) {                                        \
            float2 a = *(const float2*)((PCUR) + off0 + z * S - 2);            \
            float2 b = *(const float2*)((PCUR) + off0 + z * S + 2);            \
            lv[z] = a.y; rv[z] = b.x;                                          \
        }                                                                      \
        u64 oldcc, val;                                                        \
        if (gtop) {                                                            \
            if (lead_t && has_up) mbar_expect(mb_top[PAR], NX * 4);            \
            const u64 seamA = f2ld((PCUR) + offSA);                            \
            const u64 save0 = ccp[0];                                          \
            const u64 save1 = ccp[1];                                          \
            if (has_up && (WAITOK)) mbar_wait(mb_top[(PAR) ^ 1], (WPAR));      \
            {                                                                  \
                const u64 haloB = f2ld((PCUR) + offSB);                        \
                STEP_ROW(PNXT, 0, haloB, save1, oldcc, val);                   \
                if (has_up) {                                                  \
                    uint32_t rs = mapa32((RBASE) +                             \
                        (uint32_t)((ROWS - 1) * S + xi) * 4u, rank - 1);       \
                    uint32_t rm = mapa32(mb_bot[PAR], rank - 1);               \
                    st_async_f2(rs, rm, val);                                  \
                }                                                              \
            }                                                                  \
            u64 below = save0;                                                 \
            _Pragma("unroll")                                                  \
            for (int z = 1; z < RPT; z++) {                                    \
                u64 above = (z == RPT - 1) ? seamA : ccp[z + 1];               \
                STEP_ROW(PNXT, z, below, above, oldcc, val);                   \
                below = oldcc;                                                 \
            }                                                                  \
        } else if (gbot) {                                                     \
            if (lead_b && has_dn) mbar_expect(mb_bot[PAR], NX * 4);            \
            const u64 seamB = f2ld((PCUR) + offSB);                            \
            const u64 saveL = ccp[RPT - 1];                                    \
            u64 belowB = ccp[RPT - 2];                                         \
            if (has_dn && (WAITOK)) mbar_wait(mb_bot[(PAR) ^ 1], (WPAR));      \
            {                                                                  \
                const u64 haloA = f2ld((PCUR) + offSA);                        \
                STEP_ROW(PNXT, RPT - 1, belowB, haloA, oldcc, val);            \
                if (has_dn) {                                                  \
                    uint32_t rs = mapa32((RBASE) + (uint32_t)(xi) * 4u,        \
                                         rank + 1);                            \
                    uint32_t rm = mapa32(mb_top[PAR], rank + 1);               \
                    st_async_f2(rs, rm, val);                                  \
                }                                                              \
            }                                                                  \
            u64 below = seamB;                                                 \
            _Pragma("unroll")                                                  \
            for (int z = 0; z < RPT - 1; z++) {                                \
                u64 above = (z == RPT - 2) ? saveL : ccp[z + 1];               \
                STEP_ROW(PNXT, z, below, above, oldcc, val);                   \
                below = oldcc;                                                 \
            }                                                                  \
        } else {                                                               \
            const u64 seamA = f2ld((PCUR) + offSA);                            \
            u64 below = f2ld((PCUR) + offSB);                                  \
            _Pragma("unroll")                                                  \
            for (int z = 0; z < RPT; z++) {                                    \
                u64 above = (z == RPT - 1) ? seamA : ccp[z + 1];               \
                STEP_ROW(PNXT, z, below, above, oldcc, val);                   \
                below = oldcc;                                                 \
            }                                                                  \
        }                                                                      \
        __syncthreads();                                                       \
        if (has_rec) outp[OUTOFF] = (PNXT)[myrpos];                            \
    }

    for (int t = 0; t < NT; t += 4) {
        DO_STEP(b0, b1, base1, 0, t,     t > 0, 1, 0);
        DO_STEP(b1, b0, base0, 1, t + 1, true,  0, NR);
        DO_STEP(b0, b1, base1, 0, t + 2, true,  0, 2 * NR);
        DO_STEP(b1, b0, base0, 1, t + 3, true,  1, 3 * NR);
        outp += 4 * NR;
    }

    if (lead_t && has_up) mbar_wait(mb_top[1], 1);
    if (lead_b && has_dn) mbar_wait(mb_bot[1], 1);
    __syncthreads();
    cluster_sync_();
#undef DO_STEP
#undef STEP_ROW
}

// ============================== LAUNCHER ==================================
extern "C" void kernel_launch(void* const* d_in, const int* in_sizes, int n_in,
                              void* d_out, int out_size)
{
    const float* x     = (const float*)d_in[0];
    const float* vp    = (const float*)d_in[1];
    const int*   src_z = (const int*)d_in[2];
    const int*   src_x = (const int*)d_in[3];
    const int*   rec_z = (const int*)d_in[4];
    const int*   rec_x = (const int*)d_in[5];
    float*       out   = (float*)d_out;

    // ---- try 16 clusters x 8 CTAs x 512 threads (static smem only) ----
    bool useNew = false;
    {
        cudaLaunchConfig_t cfg = {};
        cfg.gridDim  = dim3(NS * 32, 1, 1);
        cfg.blockDim = dim3(512, 1, 1);
        cfg.dynamicSmemBytes = 0;
        cudaLaunchAttribute attr[1];
        attr[0].id = cudaLaunchAttributeClusterDimension;
        attr[0].val.clusterDim = {8, 1, 1};
        cfg.attrs = attr;
        cfg.numAttrs = 1;
        int ncl = 0;
        if (cudaOccupancyMaxActiveClusters(&ncl, wave_cl8, &cfg) == cudaSuccess
            && ncl >= 16) useNew = true;
        else cudaGetLastError();
    }

    if (useNew) {
        wave_cl8<<<NS * 32, 512>>>(x, vp, src_z, src_x, rec_z, rec_x, out);
        return;
    }

    // ---- fallback: proven single-cluster-per-shot kernel ----
    const int smem16 = 2 * (NZ / 16 + 2) * S * (int)sizeof(float);
    bool use16 = false;
    if (cudaFuncSetAttribute(wave_kernel_fb<16>,
            cudaFuncAttributeNonPortableClusterSizeAllowed, 1) == cudaSuccess &&
        cudaFuncSetAttribute(wave_kernel_fb<16>,
            cudaFuncAttributeMaxDynamicSharedMemorySize, smem16) == cudaSuccess) {
        cudaLaunchConfig_t cfg = {};
        cfg.gridDim  = dim3(NS * 16, 1, 1);
        cfg.blockDim = dim3(1024, 1, 1);
        cfg.dynamicSmemBytes = (size_t)smem16;
        cudaLaunchAttribute attr[1];
        attr[0].id = cudaLaunchAttributeClusterDimension;
        attr[0].val.clusterDim = {16, 1, 1};
        cfg.attrs = attr;
        cfg.numAttrs = 1;
        int ncl = 0;
        if (cudaOccupancyMaxActiveClusters(&ncl, wave_kernel_fb<16>, &cfg) == cudaSuccess
            && ncl >= NS) use16 = true;
        else cudaGetLastError();
    } else {
        cudaGetLastError();
    }

    if (use16) {
        wave_kernel_fb<16><<<NS * 16, 1024, smem16>>>(
            x, vp, src_z, src_x, rec_z, rec_x, out);
    } else {
        const int smem8 = 2 * (NZ / 8 + 2) * S * (int)sizeof(float);
        cudaFuncSetAttribute(wave_kernel_fb<8>,
            cudaFuncAttributeMaxDynamicSharedMemorySize, smem8);
        wave_kernel_fb<8><<<NS * 8, 1024, smem8>>>(
            x, vp, src_z, src_x, rec_z, rec_x, out);
    }
}